// round 7
// baseline (speedup 1.0000x reference)
#include <cuda_runtime.h>
#include <cuda_bf16.h>

// TransferMatrixMethod: B=256, L=64 (62 interior), W=512.
// Layer matrices [[a, ib],[ic, d]] (real a,b,c,d) closed under multiplication.
//
// ROTATION FORM (epsilons dropped: fp32(n+1e-8)==n for n>=1, so identical to
// the fp32 reference): state (A, Bt=n*B, C, Dh=-n*D). Per layer with
// r = n_next/n_cur, cpr = cp*r, mspr = -sp*r:
//   A'  = cp*A  + sp*Bt
//   Bt' = cpr*Bt + mspr*A
//   C'  = cp*C  + sp*Dh
//   Dh' = cpr*Dh + mspr*C
// Last ratio in each chunk = 1/n_last, so the chunk ends in plain form
// (Bt=B, Dh=-D=Dt), feeding the verified combine/epilogue from R5/R6.
//
// f32x2 lanes = 2 adjacent wavelengths. 4-way layer split (identity padding
// to 64 layers), combine via lane xor 8 then xor 16. 8192 warps.
//
// SOFTWARE PIPELINE: sincos of layer j+1 issued before matrix update of
// layer j, decoupling the MUFU stream from the FMA stream.

#define LTOT 64
#define WDIM 512
#define TPB  128

typedef unsigned long long u64;

__device__ __forceinline__ u64 pack2(float lo, float hi) {
    u64 r;
    asm("mov.b64 %0, {%1, %2};" : "=l"(r) : "f"(lo), "f"(hi));
    return r;
}
__device__ __forceinline__ void unpack2(float& lo, float& hi, u64 v) {
    asm("mov.b64 {%0, %1}, %2;" : "=f"(lo), "=f"(hi) : "l"(v));
}
__device__ __forceinline__ u64 mul2(u64 a, u64 b) {
    u64 r;
    asm("mul.rn.f32x2 %0, %1, %2;" : "=l"(r) : "l"(a), "l"(b));
    return r;
}
__device__ __forceinline__ u64 fma2(u64 a, u64 b, u64 c) {
    u64 r;
    asm("fma.rn.f32x2 %0, %1, %2, %3;" : "=l"(r) : "l"(a), "l"(b), "l"(c));
    return r;
}
__device__ __forceinline__ u64 neg2(u64 a) {
    return a ^ 0x8000000080000000ULL;
}

__device__ __forceinline__ void combine(u64& A, u64& B, u64& C, u64& Dt,
                                        int xm, bool upper)
{
    const unsigned FULL = 0xffffffffu;
    u64 pA  = __shfl_xor_sync(FULL, A,  xm);
    u64 pB  = __shfl_xor_sync(FULL, B,  xm);
    u64 pC  = __shfl_xor_sync(FULL, C,  xm);
    u64 pDt = __shfl_xor_sync(FULL, Dt, xm);

    u64 LA  = upper ? pA  : A;   u64 RA  = upper ? A  : pA;
    u64 LB  = upper ? pB  : B;   u64 RB  = upper ? B  : pB;
    u64 LC  = upper ? pC  : C;   u64 RC  = upper ? C  : pC;
    u64 LDt = upper ? pDt : Dt;  u64 RDt = upper ? Dt : pDt;

    u64 nLB  = neg2(LB);
    u64 nLDt = neg2(LDt);

    u64 zA  = fma2(nLB,  RC,  mul2(LA, RA));
    u64 zB  = fma2(nLB,  RDt, mul2(LA, RB));
    u64 zC  = fma2(nLDt, RC,  mul2(LC, RA));
    u64 zDt = fma2(nLDt, RDt, mul2(LC, RB));
    A = zA; B = zB; C = zC; Dt = zDt;
}

__global__ __launch_bounds__(TPB)
void tmm_kernel(const float* __restrict__ n_layers,
                const float* __restrict__ d_layers,
                const float* __restrict__ wavelengths,
                float* __restrict__ out)
{
    const int b    = blockIdx.x >> 3;        // 0..255
    const int oct  = blockIdx.x & 7;         // eighth of wavelength axis
    const int t    = threadIdx.x;            // 0..127
    const int lane = t & 31;
    const int wrp  = t >> 5;
    const int h    = lane >> 3;              // layer-split index, 0..3
    const int c    = lane & 7;
    const int chain = wrp * 8 + c;           // 0..31 in block
    const int w0   = oct * 64 + chain * 2;   // first of 2 wavelengths

    // padded layer tables: idx = 17*h + j, j in [0,16); layers 62,63 identity
    __shared__ float s_nd[68];     // n*d
    __shared__ u64   s_r2[68];     // {ratio, ratio}, ratio = n_next/n_cur
    __shared__ float s_dh0[4];     // -n_first per chunk
    __shared__ float s_nin, s_nsub;

    if (t < 64) {
        const int hh = t >> 4, j = t & 15, idx = hh * 17 + j;
        float nv = 1.0f, dv = 0.0f;
        if (t < 62) {
            nv = n_layers[b * LTOT + t + 1];
            dv = d_layers[b * LTOT + t + 1];
        }
        s_nd[idx] = nv * dv;
        float nn = 1.0f;
        if (j < 15) {
            const int Lp = t + 1;
            nn = (Lp < 62) ? n_layers[b * LTOT + Lp + 1] : 1.0f;
        }
        const float r = nn / nv;
        s_r2[idx] = pack2(r, r);
        if (j == 0) s_dh0[hh] = -nv;
    }
    if (t == 64) s_nin  = n_layers[b * LTOT];
    if (t == 65) s_nsub = n_layers[b * LTOT + LTOT - 1];
    __syncthreads();

    const float TWO_PI = 6.28318530717958647692f;
    const float2 lam = *reinterpret_cast<const float2*>(wavelengths + w0);
    const float k0 = __fdividef(TWO_PI, lam.x);
    const float k1 = __fdividef(TWO_PI, lam.y);

    const int base = h * 17;

    u64 A  = pack2(1.0f, 1.0f);
    u64 Bt = 0ULL;
    u64 C  = 0ULL;
    const float dh0 = s_dh0[h];
    u64 Dh = pack2(dh0, dh0);     // -n_first * D

    // prologue: trig for j = 0
    float sp0, cp0, sp1, cp1;
    {
        const float nd = s_nd[base];
        __sincosf(nd * k0, &sp0, &cp0);
        __sincosf(nd * k1, &sp1, &cp1);
    }

    #pragma unroll
    for (int j = 0; j < 16; ++j) {
        const u64 sp2 = pack2(sp0, sp1);
        const u64 cp2 = pack2(cp0, cp1);

        // ---- prefetch trig for layer j+1 (independent of matrix below) ----
        if (j < 15) {
            const float nd = s_nd[base + j + 1];
            __sincosf(nd * k0, &sp0, &cp0);
            __sincosf(nd * k1, &sp1, &cp1);
        }

        // ---- matrix update for layer j ----
        const u64 r2   = s_r2[base + j];
        const u64 cpr  = mul2(cp2, r2);
        const u64 mspr = neg2(mul2(sp2, r2));

        u64 nA = fma2(sp2,  Bt, mul2(cp2, A));
        u64 nB = fma2(mspr, A,  mul2(cpr, Bt));
        u64 nC = fma2(sp2,  Dh, mul2(cp2, C));
        u64 nD = fma2(mspr, C,  mul2(cpr, Dh));
        A = nA; Bt = nB; C = nC; Dh = nD;
    }
    // chunk ends in plain form: Bt = B, Dh = -D = Dt

    combine(A, Bt, C, Dh, 8,  (h & 1) != 0);
    combine(A, Bt, C, Dh, 16, (h & 2) != 0);

    if (h == 0) {
        float A0, A1, B0, B1, C0, C1, Dt0, Dt1;
        unpack2(A0, A1, A);
        unpack2(B0, B1, Bt);
        unpack2(C0, C1, C);
        unpack2(Dt0, Dt1, Dh);

        const float nin  = s_nin;
        const float nsub = s_nsub;

        float R[2];
        #pragma unroll
        for (int i = 0; i < 2; ++i) {
            const float a  = i ? A1 : A0;
            const float bb = i ? B1 : B0;
            const float c2 = i ? C1 : C0;
            const float d  = -(i ? Dt1 : Dt0);

            const float Er = a + 1e-9f;
            const float Ei = bb * nsub;
            const float Hr = d * nsub;
            const float Hi = c2;

            const float numr = fmaf(nin, Er, -Hr);
            const float numi = fmaf(nin, Ei, -Hi);
            const float denr = fmaf(nin, Er,  Hr);
            const float deni = fmaf(nin, Ei,  Hi);

            const float num2 = fmaf(numr, numr, numi * numi);
            const float den2 = fmaf(denr, denr, deni * deni);
            R[i] = num2 / den2;
        }

        *reinterpret_cast<float2*>(out + b * WDIM + w0) = make_float2(R[0], R[1]);
    }
}

extern "C" void kernel_launch(void* const* d_in, const int* in_sizes, int n_in,
                              void* d_out, int out_size)
{
    const float* n_layers    = (const float*)d_in[0];  // (256, 64)
    const float* d_layers    = (const float*)d_in[1];  // (256, 64)
    const float* wavelengths = (const float*)d_in[2];  // (512,)
    float* out = (float*)d_out;                        // (256, 512)

    tmm_kernel<<<2048, TPB>>>(n_layers, d_layers, wavelengths, out);
}